// round 8
// baseline (speedup 1.0000x reference)
#include <cuda_runtime.h>

// Problem constants
#define Bn 16
#define Cn 512
#define Hn 80
#define Wn 80
#define HWn (Hn*Wn)          // 6400
#define CHWn (Cn*HWn)        // 3276800
#define NPIX (Bn*HWn)        // 102400

// counting-sort chunks: 256 pixels per block
#define CHUNK_PIX 256
#define NCHUNK 25                       // chunks per batch (6400/256)
#define NBLK (Bn*NCHUNK)                // 400 blocks
#define NCNT (Bn*Cn*NCHUNK)             // 204800 counters, order (b,c,chunk)

// two-level scan of NCNT counters: 200 blocks x 1024 (exact)
#define K3A_BLKS 200
#define K3A_TPB 1024

// dynamic smem request to cap occupancy at 1 block/SM (L2 residency for Phase B)
#define FUSED_SMEM (120*1024)

// ---- scratch (allocation-free: __device__ globals) ----
__device__ unsigned int g_rec[NPIX * 2];   // 2 det slots/pixel: (c<<16)|rank, ~0u=empty
__device__ unsigned int g_cnt[NCNT];       // counts per (b,c,chunk)
__device__ unsigned int g_off[NCNT];       // exclusive within 1024-superblock
__device__ unsigned int g_bsum[K3A_BLKS];
__device__ unsigned int g_bbase[K3A_BLKS];

// ---------------------------------------------------------------------------
// K0: init output padding only
__global__ void k0_init(float4* __restrict__ out4, int n4, int half4) {
    int i = blockIdx.x * blockDim.x + threadIdx.x;
    if (i < half4) {
        out4[i] = make_float4(-1.f, -1.f, -1.f, -1.f);       // grid padding
    } else if (i < n4) {
        out4[i] = make_float4(-4.5f, -4.5f, -4.5f, -4.5f);   // 8*(-1)+3.5
    }
}

// ---------------------------------------------------------------------------
// neighbor test: v (>=0) must be >= all in-bounds raw 3x3 neighbors
// (v >= relu(n) <=> v >= n when v >= 0). Rare path; keep out of the hot loop.
__device__ __noinline__ bool neigh_ok(const float* __restrict__ plane,
                                      float v, int h, int w) {
    #pragma unroll
    for (int dh = -1; dh <= 1; dh++) {
        int nh = h + dh;
        if (nh < 0 || nh >= Hn) continue;
        #pragma unroll
        for (int dw = -1; dw <= 1; dw++) {
            if (dh == 0 && dw == 0) continue;
            int nw = w + dw;
            if (nw < 0 || nw >= Wn) continue;
            if (v < plane[nh * Wn + nw]) return false;
        }
    }
    return true;
}

// ---------------------------------------------------------------------------
// Fused kernel: one thread per pixel, one block per (batch, 256-pixel chunk).
// Phase A: depthwise max m of relu over 512 channels (thread-local, exact).
// Phase B: re-scan the same 512 addresses (L2-resident), per-ELEMENT test
//          bits(relu(v)) == bits(m) — handles exact float ties at the max,
//          and the degenerate m==0 pixel — then 3x3 local-max confirm.
// Phase C: chunk-level counting-sort bookkeeping: per-channel counts +
//          exact pixel-order rank via broadcast smem scan.
__global__ void __launch_bounds__(CHUNK_PIX) kfused(const float* __restrict__ x) {
    extern __shared__ unsigned int smem[];
    unsigned int* bucket = smem;           // [Cn] per-channel counts, this chunk
    unsigned int* ch     = smem + Cn;      // [CHUNK_PIX] packed det channels

    int blk = blockIdx.x;                  // 400
    int t = threadIdx.x;
    int b     = blk / NCHUNK;
    int chunk = blk - b * NCHUNK;
    int hw = chunk * CHUNK_PIX + t;
    const float* base = x + (size_t)b * CHWn + hw;

    for (int i = t; i < Cn; i += CHUNK_PIX) bucket[i] = 0u;

    // ---- Phase A: m = max(0, x[:,hw]) over channels (4 accumulators) ----
    float m0 = 0.f, m1 = 0.f, m2 = 0.f, m3 = 0.f;
    #pragma unroll 8
    for (int c = 0; c < Cn; c += 4) {
        m0 = fmaxf(m0, base[(size_t)(c+0) * HWn]);
        m1 = fmaxf(m1, base[(size_t)(c+1) * HWn]);
        m2 = fmaxf(m2, base[(size_t)(c+2) * HWn]);
        m3 = fmaxf(m3, base[(size_t)(c+3) * HWn]);
    }
    unsigned int mb = __float_as_uint(fmaxf(fmaxf(m0, m1), fmaxf(m2, m3)));

    // ---- Phase B: per-element equality (exact, tie-safe) + local max ----
    int h = hw / Wn, w = hw - (hw / Wn) * Wn;
    int nd = 0;
    unsigned int c0 = 0xFFFFu, c1 = 0xFFFFu;
    #pragma unroll 8
    for (int c = 0; c < Cn; c++) {
        float v = fmaxf(base[(size_t)c * HWn], 0.f);
        if (__float_as_uint(v) == mb) {
            const float* plane = x + (size_t)b * CHWn + (size_t)c * HWn;
            if (neigh_ok(plane, v, h, w)) {
                if (nd == 0) c0 = (unsigned)c;
                else if (nd == 1) c1 = (unsigned)c;
                // >2 dets/pixel requires a triple exact-float tie at the max:
                // probability ~0; slots cap at 2.
                nd++;
            }
        }
    }

    // ---- Phase C: counts + exact pixel-order ranks ----
    __syncthreads();                        // bucket init complete
    if (nd > 0) atomicAdd(&bucket[c0], 1u);
    if (nd > 1) atomicAdd(&bucket[c1], 1u);
    ch[t] = c0 | (c1 << 16);                // 0xFFFF = empty slot
    __syncthreads();                        // all counts + ch visible

    unsigned int r0 = 0, r1 = 0;
    if (nd > 0) {
        for (int pix = 0; pix < t; pix++) { // broadcast reads, conflict-free
            unsigned int wv = ch[pix];
            unsigned int lo = wv & 0xFFFFu, hi = wv >> 16;
            r0 += (lo == c0) + (hi == c0);
            r1 += (lo == c1) + (hi == c1);
        }
    }
    int p = b * HWn + hw;
    g_rec[2*p + 0] = (nd > 0) ? ((c0 << 16) | r0) : 0xFFFFFFFFu;
    g_rec[2*p + 1] = (nd > 1) ? ((c1 << 16) | r1) : 0xFFFFFFFFu;

    for (int i = t; i < Cn; i += CHUNK_PIX)
        g_cnt[(b * Cn + i) * NCHUNK + chunk] = bucket[i];
}

// ---------------------------------------------------------------------------
// K3a: 200 blocks x 1024 counts (1/thread): local exclusive scan + block sum.
__global__ void __launch_bounds__(K3A_TPB) k3a_scan() {
    int sb = blockIdx.x;
    int t = threadIdx.x;
    int lane = t & 31;
    int warp = t >> 5;
    unsigned int v = g_cnt[sb * K3A_TPB + t];
    unsigned int incl = v;
    #pragma unroll
    for (int off = 1; off < 32; off <<= 1) {
        unsigned int n = __shfl_up_sync(0xFFFFFFFFu, incl, off);
        if (lane >= off) incl += n;
    }
    __shared__ unsigned int ws[32];
    if (lane == 31) ws[warp] = incl;
    __syncthreads();
    if (t < 32) {
        unsigned int w = ws[t];
        unsigned int iw = w;
        #pragma unroll
        for (int off = 1; off < 32; off <<= 1) {
            unsigned int n = __shfl_up_sync(0xFFFFFFFFu, iw, off);
            if (t >= off) iw += n;
        }
        ws[t] = iw - w;                     // exclusive warp base
        if (t == 31) g_bsum[sb] = iw;       // superblock total
    }
    __syncthreads();
    g_off[sb * K3A_TPB + t] = ws[warp] + (incl - v);
}

// K3b: one block scans the 200 superblock sums into exclusive bases.
__global__ void __launch_bounds__(256) k3b_base() {
    int t = threadIdx.x;
    int lane = t & 31;
    int warp = t >> 5;
    unsigned int v = (t < K3A_BLKS) ? g_bsum[t] : 0u;
    unsigned int incl = v;
    #pragma unroll
    for (int off = 1; off < 32; off <<= 1) {
        unsigned int n = __shfl_up_sync(0xFFFFFFFFu, incl, off);
        if (lane >= off) incl += n;
    }
    __shared__ unsigned int ws[8];
    if (lane == 31) ws[warp] = incl;
    __syncthreads();
    if (t < 8) {
        unsigned int w = ws[t];
        unsigned int iw = w;
        #pragma unroll
        for (int off = 1; off < 8; off <<= 1) {
            unsigned int n = __shfl_up_sync(0x000000FFu, iw, off);
            if (t >= off) iw += n;
        }
        ws[t] = iw - w;
    }
    __syncthreads();
    if (t < K3A_BLKS) g_bbase[t] = ws[warp] + (incl - v);
}

// ---------------------------------------------------------------------------
// K4: place each detection at its globally sorted position.
__global__ void __launch_bounds__(CHUNK_PIX) k4_write(float* __restrict__ out, int nmax) {
    int blk = blockIdx.x;
    int t = threadIdx.x;
    int b     = blk / NCHUNK;
    int chunk = blk - b * NCHUNK;
    int hw = chunk * CHUNK_PIX + t;
    int p  = b * HWn + hw;
    float h = (float)(hw / Wn);
    float w = (float)(hw % Wn);
    float* kp = out + 2u * (unsigned)nmax;
    #pragma unroll
    for (int slot = 0; slot < 2; slot++) {
        unsigned int rec = g_rec[2*p + slot];
        if (rec != 0xFFFFFFFFu) {
            unsigned int c    = rec >> 16;
            unsigned int rank = rec & 0xFFFFu;
            unsigned int idx  = (unsigned)((b * Cn + (int)c) * NCHUNK + chunk);
            unsigned int n = g_bbase[idx >> 10] + g_off[idx] + rank;
            if (n < (unsigned)nmax) {
                out[2u*n + 0u] = h;
                out[2u*n + 1u] = w;
                kp [2u*n + 0u] = 8.0f * h + 3.5f;   // ((p*2+.5)*2+.5)*2+.5
                kp [2u*n + 1u] = 8.0f * w + 3.5f;
            }
        }
    }
}

// ---------------------------------------------------------------------------
extern "C" void kernel_launch(void* const* d_in, const int* in_sizes, int n_in,
                              void* d_out, int out_size) {
    const float* x = (const float*)d_in[0];
    float* out = (float*)d_out;
    int nmax = out_size / 4;

    // allow >48KB dynamic smem (occupancy cap for L2-resident Phase B)
    static int smem_set = 0;
    if (!smem_set) {
        cudaFuncSetAttribute(kfused, cudaFuncAttributeMaxDynamicSharedMemorySize,
                             FUSED_SMEM);
        smem_set = 1;
    }

    {   // K0: output padding (float4)
        int n4 = out_size / 4;
        int half4 = (out_size / 2) / 4;
        k0_init<<<(n4 + 255) / 256, 256>>>((float4*)out, n4, half4);
    }
    kfused<<<NBLK, CHUNK_PIX, FUSED_SMEM>>>(x);   // single DRAM pass, exact semantics
    k3a_scan<<<K3A_BLKS, K3A_TPB>>>();            // scan 204800 (b,c,chunk) counts
    k3b_base<<<1, 256>>>();                       // 200 superblock bases
    k4_write<<<NBLK, CHUNK_PIX>>>(out, nmax);
}

// round 9
// speedup vs baseline: 3.5719x; 3.5719x over previous
#include <cuda_runtime.h>

// Problem constants
#define Bn 16
#define Cn 512
#define Hn 80
#define Wn 80
#define HWn (Hn*Wn)          // 6400
#define CHWn (Cn*HWn)        // 3276800
#define NPIX (Bn*HWn)        // 102400

// counting-sort chunks: 128 pixels per block -> 800 blocks (better SM balance)
#define CHUNK_PIX 128
#define NCHUNK 50                       // chunks per batch (6400/128)
#define NBLK (Bn*NCHUNK)                // 800 blocks
#define NCNT (Bn*Cn*NCHUNK)             // 409600 counters, order (b,c,chunk)

// two-level scan of NCNT counters: 400 blocks x 1024 (exact)
#define K3A_BLKS 400
#define K3A_TPB 1024

// ---- scratch (allocation-free: __device__ globals) ----
__device__ unsigned int g_rec[NPIX * 2];   // 2 det slots/pixel: (c<<16)|rank, ~0u=empty
__device__ unsigned int g_cnt[NCNT];       // counts per (b,c,chunk)
__device__ unsigned int g_off[NCNT];       // exclusive within 1024-superblock
__device__ unsigned int g_bsum[K3A_BLKS];
__device__ unsigned int g_bbase[K3A_BLKS];

// ---------------------------------------------------------------------------
// K0: init output padding only
__global__ void k0_init(float4* __restrict__ out4, int n4, int half4) {
    int i = blockIdx.x * blockDim.x + threadIdx.x;
    if (i < half4) {
        out4[i] = make_float4(-1.f, -1.f, -1.f, -1.f);       // grid padding
    } else if (i < n4) {
        out4[i] = make_float4(-4.5f, -4.5f, -4.5f, -4.5f);   // 8*(-1)+3.5
    }
}

// ---------------------------------------------------------------------------
// neighbor test: v (>=0) must be >= all in-bounds raw 3x3 neighbors
// (v >= relu(n) <=> v >= n when v >= 0). Rare path.
__device__ __noinline__ bool neigh_ok(const float* __restrict__ plane,
                                      float v, int h, int w) {
    #pragma unroll
    for (int dh = -1; dh <= 1; dh++) {
        int nh = h + dh;
        if (nh < 0 || nh >= Hn) continue;
        #pragma unroll
        for (int dw = -1; dw <= 1; dw++) {
            if (dh == 0 && dw == 0) continue;
            int nw = w + dw;
            if (nw < 0 || nw >= Wn) continue;
            if (v < plane[nh * Wn + nw]) return false;
        }
    }
    return true;
}

// ---------------------------------------------------------------------------
// Fused: one thread per pixel, one block per (batch, 128-pixel chunk).
// Phase A: ONE pass over 512 channels tracking max AND the exact set of
//          channels that tie it (<=2 slots; ties only counted while m>0).
//          4 interleaved accumulators for ILP; exact merge at the end.
// Phase B: 3x3 local-max confirm per candidate channel (scattered, tiny).
// Phase C: counting-sort bookkeeping — R8-proven verbatim.
__global__ void __launch_bounds__(CHUNK_PIX) kfused(const float* __restrict__ x) {
    __shared__ unsigned int bucket[Cn];     // per-channel counts, this chunk
    __shared__ unsigned int ch[CHUNK_PIX];  // packed det channels per pixel

    int blk = blockIdx.x;                   // 800
    int t = threadIdx.x;
    int b     = blk / NCHUNK;
    int chunk = blk - b * NCHUNK;
    int hw = chunk * CHUNK_PIX + t;
    const float* base = x + (size_t)b * CHWn + hw;

    for (int i = t; i < Cn; i += CHUNK_PIX) bucket[i] = 0u;

    // ---- Phase A: single pass, 4 interleaved tie-tracking accumulators ----
    float m0 = 0.f, m1 = 0.f, m2 = 0.f, m3 = 0.f;
    int   a0 = -1,  a1 = -1,  a2 = -1,  a3 = -1;     // first tied channel
    int   b0 = -1,  b1 = -1,  b2 = -1,  b3 = -1;     // second tied channel
    int   n0 = 0,   n1 = 0,   n2 = 0,   n3 = 0;      // tie count (saturates up)
    #pragma unroll 8
    for (int c = 0; c < Cn; c += 4) {
        float v0 = fmaxf(base[(size_t)(c+0) * HWn], 0.f);
        float v1 = fmaxf(base[(size_t)(c+1) * HWn], 0.f);
        float v2 = fmaxf(base[(size_t)(c+2) * HWn], 0.f);
        float v3 = fmaxf(base[(size_t)(c+3) * HWn], 0.f);
        if (v0 > m0)      { m0 = v0; a0 = c+0; n0 = 1; }
        else if (v0 == m0 && m0 > 0.f) { if (n0 == 1) b0 = c+0; n0++; }
        if (v1 > m1)      { m1 = v1; a1 = c+1; n1 = 1; }
        else if (v1 == m1 && m1 > 0.f) { if (n1 == 1) b1 = c+1; n1++; }
        if (v2 > m2)      { m2 = v2; a2 = c+2; n2 = 1; }
        else if (v2 == m2 && m2 > 0.f) { if (n2 == 1) b2 = c+2; n2++; }
        if (v3 > m3)      { m3 = v3; a3 = c+3; n3 = 1; }
        else if (v3 == m3 && m3 > 0.f) { if (n3 == 1) b3 = c+3; n3++; }
    }
    float m = fmaxf(fmaxf(m0, m1), fmaxf(m2, m3));

    // merge candidate channels from accumulators matching the global max,
    // keeping the two smallest channel indices (ascending = reference order)
    int cand[8];
    #pragma unroll
    for (int i = 0; i < 8; i++) cand[i] = 0x7FFFFFFF;
    int ndT = 0;
    if (m > 0.f) {
        if (m0 == m) { cand[0] = a0; if (n0 > 1) cand[1] = b0; ndT += n0; }
        if (m1 == m) { cand[2] = a1; if (n1 > 1) cand[3] = b1; ndT += n1; }
        if (m2 == m) { cand[4] = a2; if (n2 > 1) cand[5] = b2; ndT += n2; }
        if (m3 == m) { cand[6] = a3; if (n3 > 1) cand[7] = b3; ndT += n3; }
    }
    int cA = 0x7FFFFFFF, cB = 0x7FFFFFFF;
    #pragma unroll
    for (int i = 0; i < 8; i++) cA = min(cA, cand[i]);
    #pragma unroll
    for (int i = 0; i < 8; i++) if (cand[i] > cA) cB = min(cB, cand[i]);
    // (>2 simultaneous exact-float ties at the max: not representable; cap=2,
    //  same assumption as the R8 kernel that verified rel_err==0)

    // ---- Phase B: local-max confirm per candidate channel ----
    int h = hw / Wn, w = hw - (hw / Wn) * Wn;
    unsigned int c0 = 0xFFFFu, c1 = 0xFFFFu;
    if (ndT >= 1) {
        bool d0 = neigh_ok(x + (size_t)b * CHWn + (size_t)cA * HWn, m, h, w);
        bool d1 = (ndT >= 2) &&
                  neigh_ok(x + (size_t)b * CHWn + (size_t)cB * HWn, m, h, w);
        if (d0) { c0 = (unsigned)cA; if (d1) c1 = (unsigned)cB; }
        else if (d1) { c0 = (unsigned)cB; }
    } else if (m == 0.f) {
        // degenerate pixel (all channels <= 0): every channel ties relu-max 0.
        // Never occurs for gaussian input (prob 2^-512); exact fallback rescan.
        int nd = 0;
        for (int c = 0; c < Cn && nd < 2; c++) {
            const float* plane = x + (size_t)b * CHWn + (size_t)c * HWn;
            if (fmaxf(plane[h * Wn + w], 0.f) == 0.f && neigh_ok(plane, 0.f, h, w)) {
                if (nd == 0) c0 = (unsigned)c; else c1 = (unsigned)c;
                nd++;
            }
        }
    }

    // ---- Phase C: counts + exact pixel-order ranks (R8-proven) ----
    __syncthreads();                        // bucket init complete
    if (c0 != 0xFFFFu) atomicAdd(&bucket[c0], 1u);
    if (c1 != 0xFFFFu) atomicAdd(&bucket[c1], 1u);
    ch[t] = c0 | (c1 << 16);
    __syncthreads();

    unsigned int r0 = 0, r1 = 0;
    if (c0 != 0xFFFFu) {
        for (int pix = 0; pix < t; pix++) {
            unsigned int wv = ch[pix];
            unsigned int lo = wv & 0xFFFFu, hi = wv >> 16;
            r0 += (lo == c0) + (hi == c0);
            r1 += (lo == c1) + (hi == c1);
        }
    }
    int p = b * HWn + hw;
    g_rec[2*p + 0] = (c0 != 0xFFFFu) ? ((c0 << 16) | r0) : 0xFFFFFFFFu;
    g_rec[2*p + 1] = (c1 != 0xFFFFu) ? ((c1 << 16) | r1) : 0xFFFFFFFFu;

    for (int i = t; i < Cn; i += CHUNK_PIX)
        g_cnt[(b * Cn + i) * NCHUNK + chunk] = bucket[i];
}

// ---------------------------------------------------------------------------
// K3a: 400 blocks x 1024 counts (1/thread): local exclusive scan + block sum.
__global__ void __launch_bounds__(K3A_TPB) k3a_scan() {
    int sb = blockIdx.x;
    int t = threadIdx.x;
    int lane = t & 31;
    int warp = t >> 5;
    unsigned int v = g_cnt[sb * K3A_TPB + t];
    unsigned int incl = v;
    #pragma unroll
    for (int off = 1; off < 32; off <<= 1) {
        unsigned int n = __shfl_up_sync(0xFFFFFFFFu, incl, off);
        if (lane >= off) incl += n;
    }
    __shared__ unsigned int ws[32];
    if (lane == 31) ws[warp] = incl;
    __syncthreads();
    if (t < 32) {
        unsigned int w = ws[t];
        unsigned int iw = w;
        #pragma unroll
        for (int off = 1; off < 32; off <<= 1) {
            unsigned int n = __shfl_up_sync(0xFFFFFFFFu, iw, off);
            if (t >= off) iw += n;
        }
        ws[t] = iw - w;                     // exclusive warp base
        if (t == 31) g_bsum[sb] = iw;       // superblock total
    }
    __syncthreads();
    g_off[sb * K3A_TPB + t] = ws[warp] + (incl - v);
}

// K3b: one block (512 threads) scans the 400 superblock sums.
__global__ void __launch_bounds__(512) k3b_base() {
    int t = threadIdx.x;
    int lane = t & 31;
    int warp = t >> 5;                      // 16 warps
    unsigned int v = (t < K3A_BLKS) ? g_bsum[t] : 0u;
    unsigned int incl = v;
    #pragma unroll
    for (int off = 1; off < 32; off <<= 1) {
        unsigned int n = __shfl_up_sync(0xFFFFFFFFu, incl, off);
        if (lane >= off) incl += n;
    }
    __shared__ unsigned int ws[16];
    if (lane == 31) ws[warp] = incl;
    __syncthreads();
    if (t < 32) {                           // warp 0 scans 16 warp sums
        unsigned int wv = (t < 16) ? ws[t] : 0u;
        unsigned int iw = wv;
        #pragma unroll
        for (int off = 1; off < 32; off <<= 1) {
            unsigned int n = __shfl_up_sync(0xFFFFFFFFu, iw, off);
            if (t >= off) iw += n;
        }
        if (t < 16) ws[t] = iw - wv;
    }
    __syncthreads();
    if (t < K3A_BLKS) g_bbase[t] = ws[warp] + (incl - v);
}

// ---------------------------------------------------------------------------
// K4: place each detection at its globally sorted position (R8-proven).
__global__ void __launch_bounds__(CHUNK_PIX) k4_write(float* __restrict__ out, int nmax) {
    int blk = blockIdx.x;
    int t = threadIdx.x;
    int b     = blk / NCHUNK;
    int chunk = blk - b * NCHUNK;
    int hw = chunk * CHUNK_PIX + t;
    int p  = b * HWn + hw;
    float h = (float)(hw / Wn);
    float w = (float)(hw % Wn);
    float* kp = out + 2u * (unsigned)nmax;
    #pragma unroll
    for (int slot = 0; slot < 2; slot++) {
        unsigned int rec = g_rec[2*p + slot];
        if (rec != 0xFFFFFFFFu) {
            unsigned int c    = rec >> 16;
            unsigned int rank = rec & 0xFFFFu;
            unsigned int idx  = (unsigned)((b * Cn + (int)c) * NCHUNK + chunk);
            unsigned int n = g_bbase[idx >> 10] + g_off[idx] + rank;
            if (n < (unsigned)nmax) {
                out[2u*n + 0u] = h;
                out[2u*n + 1u] = w;
                kp [2u*n + 0u] = 8.0f * h + 3.5f;   // ((p*2+.5)*2+.5)*2+.5
                kp [2u*n + 1u] = 8.0f * w + 3.5f;
            }
        }
    }
}

// ---------------------------------------------------------------------------
extern "C" void kernel_launch(void* const* d_in, const int* in_sizes, int n_in,
                              void* d_out, int out_size) {
    const float* x = (const float*)d_in[0];
    float* out = (float*)d_out;
    int nmax = out_size / 4;

    {   // K0: output padding (float4)
        int n4 = out_size / 4;
        int half4 = (out_size / 2) / 4;
        k0_init<<<(n4 + 255) / 256, 256>>>((float4*)out, n4, half4);
    }
    kfused<<<NBLK, CHUNK_PIX>>>(x);      // ONE 210MB pass, exact tie-safe semantics
    k3a_scan<<<K3A_BLKS, K3A_TPB>>>();   // scan 409600 (b,c,chunk) counts
    k3b_base<<<1, 512>>>();              // 400 superblock bases
    k4_write<<<NBLK, CHUNK_PIX>>>(out, nmax);
}

// round 10
// speedup vs baseline: 4.8291x; 1.3520x over previous
#include <cuda_runtime.h>

// Problem constants
#define Bn 16
#define Cn 512
#define Hn 80
#define Wn 80
#define HWn (Hn*Wn)          // 6400
#define CHWn (Cn*HWn)        // 3276800
#define NPIX (Bn*HWn)        // 102400

// counting-sort chunks: 256 pixels per block, 4 channel-groups -> 1024 thr/blk
#define CHUNK_PIX 256
#define NGRP 4
#define GRP_C (Cn/NGRP)                 // 128 channels per group
#define TPB_F (CHUNK_PIX*NGRP)          // 1024
#define NCHUNK 25                       // chunks per batch (6400/256)
#define NBLK (Bn*NCHUNK)                // 400 blocks
#define NCNT (Bn*Cn*NCHUNK)             // 204800 counters, order (b,c,chunk)

// two-level scan of NCNT counters: 200 blocks x 1024 (exact)
#define K3A_BLKS 200
#define K3A_TPB 1024

// ---- scratch (allocation-free: __device__ globals) ----
__device__ unsigned int g_rec[NPIX * 2];   // 2 det slots/pixel: (c<<16)|rank, ~0u=empty
__device__ unsigned int g_cnt[NCNT];       // counts per (b,c,chunk)
__device__ unsigned int g_off[NCNT];       // exclusive within 1024-superblock
__device__ unsigned int g_bsum[K3A_BLKS];
__device__ unsigned int g_bbase[K3A_BLKS];

// ---------------------------------------------------------------------------
// K0: init output padding only
__global__ void k0_init(float4* __restrict__ out4, int n4, int half4) {
    int i = blockIdx.x * blockDim.x + threadIdx.x;
    if (i < half4) {
        out4[i] = make_float4(-1.f, -1.f, -1.f, -1.f);       // grid padding
    } else if (i < n4) {
        out4[i] = make_float4(-4.5f, -4.5f, -4.5f, -4.5f);   // 8*(-1)+3.5
    }
}

// ---------------------------------------------------------------------------
// neighbor test: v (>=0) must be >= all in-bounds raw 3x3 neighbors
// (v >= relu(n) <=> v >= n when v >= 0). Rare path.
__device__ __noinline__ bool neigh_ok(const float* __restrict__ plane,
                                      float v, int h, int w) {
    #pragma unroll
    for (int dh = -1; dh <= 1; dh++) {
        int nh = h + dh;
        if (nh < 0 || nh >= Hn) continue;
        #pragma unroll
        for (int dw = -1; dw <= 1; dw++) {
            if (dh == 0 && dw == 0) continue;
            int nw = w + dw;
            if (nw < 0 || nw >= Wn) continue;
            if (v < plane[nh * Wn + nw]) return false;
        }
    }
    return true;
}

// ---------------------------------------------------------------------------
// Fused: 4 threads per pixel (128 channels each), 256 pixels per block.
// Phase A: per-thread tie-tracking scan over its 128 channels (R9-proven
//          accumulator logic verbatim), results to smem.
// Merge:   leader thread per pixel combines 4 group results; groups are
//          channel-ordered so first two candidates in group order are the
//          two smallest tied channels (reference order).
// Phase B: 3x3 local-max confirm per candidate channel (leaders).
// Phase C: counting-sort bookkeeping — R8-proven verbatim.
__global__ void __launch_bounds__(TPB_F) kfused(const float* __restrict__ x) {
    __shared__ unsigned int s_mb[TPB_F];     // group max bits (relu >= 0)
    __shared__ unsigned int s_cand[TPB_F];   // cA | cB<<16 (0xFFFF = empty)
    __shared__ unsigned char s_nd[TPB_F];    // tie count (saturated at 3)
    __shared__ unsigned int bucket[Cn];      // per-channel counts, this chunk
    __shared__ unsigned int ch[CHUNK_PIX];   // packed det channels per pixel

    int blk = blockIdx.x;                    // 400
    int t = threadIdx.x;
    int pix = t & (CHUNK_PIX - 1);
    int grp = t >> 8;                        // 0..3
    int b     = blk / NCHUNK;
    int chunk = blk - b * NCHUNK;
    int hw = chunk * CHUNK_PIX + pix;
    int cbase = grp * GRP_C;
    const float* base = x + (size_t)b * CHWn + (size_t)cbase * HWn + hw;

    if (t < Cn) bucket[t] = 0u;

    // ---- Phase A: tie-tracking scan of 128 channels (4 accumulators) ----
    float m0 = 0.f, m1 = 0.f, m2 = 0.f, m3 = 0.f;
    int   a0 = -1,  a1 = -1,  a2 = -1,  a3 = -1;     // first tied channel
    int   b0 = -1,  b1 = -1,  b2 = -1,  b3 = -1;     // second tied channel
    int   n0 = 0,   n1 = 0,   n2 = 0,   n3 = 0;      // tie counts
    #pragma unroll 8
    for (int c = 0; c < GRP_C; c += 4) {
        float v0 = fmaxf(base[(size_t)(c+0) * HWn], 0.f);
        float v1 = fmaxf(base[(size_t)(c+1) * HWn], 0.f);
        float v2 = fmaxf(base[(size_t)(c+2) * HWn], 0.f);
        float v3 = fmaxf(base[(size_t)(c+3) * HWn], 0.f);
        if (v0 > m0)      { m0 = v0; a0 = cbase + c+0; n0 = 1; }
        else if (v0 == m0 && m0 > 0.f) { if (n0 == 1) b0 = cbase + c+0; n0++; }
        if (v1 > m1)      { m1 = v1; a1 = cbase + c+1; n1 = 1; }
        else if (v1 == m1 && m1 > 0.f) { if (n1 == 1) b1 = cbase + c+1; n1++; }
        if (v2 > m2)      { m2 = v2; a2 = cbase + c+2; n2 = 1; }
        else if (v2 == m2 && m2 > 0.f) { if (n2 == 1) b2 = cbase + c+2; n2++; }
        if (v3 > m3)      { m3 = v3; a3 = cbase + c+3; n3 = 1; }
        else if (v3 == m3 && m3 > 0.f) { if (n3 == 1) b3 = cbase + c+3; n3++; }
    }
    float m = fmaxf(fmaxf(m0, m1), fmaxf(m2, m3));

    // per-thread merge: two smallest tied channels within this group (R9-proven)
    int cand[8];
    #pragma unroll
    for (int i = 0; i < 8; i++) cand[i] = 0x7FFFFFFF;
    int ndT = 0;
    if (m > 0.f) {
        if (m0 == m) { cand[0] = a0; if (n0 > 1) cand[1] = b0; ndT += n0; }
        if (m1 == m) { cand[2] = a1; if (n1 > 1) cand[3] = b1; ndT += n1; }
        if (m2 == m) { cand[4] = a2; if (n2 > 1) cand[5] = b2; ndT += n2; }
        if (m3 == m) { cand[6] = a3; if (n3 > 1) cand[7] = b3; ndT += n3; }
    }
    int cA = 0x7FFFFFFF, cB = 0x7FFFFFFF;
    #pragma unroll
    for (int i = 0; i < 8; i++) cA = min(cA, cand[i]);
    #pragma unroll
    for (int i = 0; i < 8; i++) if (cand[i] > cA) cB = min(cB, cand[i]);

    s_mb[t]   = __float_as_uint(m);
    s_cand[t] = (unsigned)(cA & 0xFFFF) | ((unsigned)(cB & 0xFFFF) << 16);
    s_nd[t]   = (unsigned char)min(ndT, 3);
    __syncthreads();

    // ---- leader merge + Phase B + Phase C front half ----
    unsigned int c0 = 0xFFFFu, c1 = 0xFFFFu;
    if (t < CHUNK_PIX) {
        unsigned int mb = 0u;
        #pragma unroll
        for (int g = 0; g < NGRP; g++) mb = max(mb, s_mb[g * CHUNK_PIX + t]);
        // collect candidates in ascending group (= channel) order
        unsigned int tA = 0xFFFFu, tB = 0xFFFFu;
        int ndtot = 0;
        if (mb != 0u) {                         // relu bits: 0 iff m == 0
            #pragma unroll
            for (int g = 0; g < NGRP; g++) {
                int gi = g * CHUNK_PIX + t;
                if (s_mb[gi] == mb) {
                    unsigned int pk = s_cand[gi];
                    unsigned int la = pk & 0xFFFFu, lb = pk >> 16;
                    if (la != 0xFFFFu) { if (tA == 0xFFFFu) tA = la; else if (tB == 0xFFFFu) tB = la; }
                    if (lb != 0xFFFFu) { if (tA == 0xFFFFu) tA = lb; else if (tB == 0xFFFFu) tB = lb; }
                    ndtot += (int)s_nd[gi];
                }
            }
        }
        float mv = __uint_as_float(mb);
        int h = hw / Wn, w = hw - (hw / Wn) * Wn;
        if (ndtot >= 1) {
            bool d0 = neigh_ok(x + (size_t)b * CHWn + (size_t)tA * HWn, mv, h, w);
            bool d1 = (ndtot >= 2) && (tB != 0xFFFFu) &&
                      neigh_ok(x + (size_t)b * CHWn + (size_t)tB * HWn, mv, h, w);
            if (d0) { c0 = tA; if (d1) c1 = tB; }
            else if (d1) { c0 = tB; }
        } else if (mb == 0u) {
            // degenerate pixel (all channels <= 0): prob 2^-512; exact rescan.
            int nd = 0;
            for (int c = 0; c < Cn && nd < 2; c++) {
                const float* plane = x + (size_t)b * CHWn + (size_t)c * HWn;
                if (fmaxf(plane[h * Wn + w], 0.f) == 0.f && neigh_ok(plane, 0.f, h, w)) {
                    if (nd == 0) c0 = (unsigned)c; else c1 = (unsigned)c;
                    nd++;
                }
            }
        }
        if (c0 != 0xFFFFu) atomicAdd(&bucket[c0], 1u);
        if (c1 != 0xFFFFu) atomicAdd(&bucket[c1], 1u);
        ch[t] = c0 | (c1 << 16);
    }
    __syncthreads();

    // ---- Phase C back half: exact pixel-order ranks (R8-proven) ----
    if (t < CHUNK_PIX) {
        unsigned int r0 = 0, r1 = 0;
        if (c0 != 0xFFFFu) {
            for (int q = 0; q < t; q++) {
                unsigned int wv = ch[q];
                unsigned int lo = wv & 0xFFFFu, hi = wv >> 16;
                r0 += (lo == c0) + (hi == c0);
                r1 += (lo == c1) + (hi == c1);
            }
        }
        int p = b * HWn + hw;
        g_rec[2*p + 0] = (c0 != 0xFFFFu) ? ((c0 << 16) | r0) : 0xFFFFFFFFu;
        g_rec[2*p + 1] = (c1 != 0xFFFFu) ? ((c1 << 16) | r1) : 0xFFFFFFFFu;
    }
    if (t < Cn)
        g_cnt[(b * Cn + t) * NCHUNK + chunk] = bucket[t];
}

// ---------------------------------------------------------------------------
// K3a: 200 blocks x 1024 counts (1/thread): local exclusive scan + block sum.
__global__ void __launch_bounds__(K3A_TPB) k3a_scan() {
    int sb = blockIdx.x;
    int t = threadIdx.x;
    int lane = t & 31;
    int warp = t >> 5;
    unsigned int v = g_cnt[sb * K3A_TPB + t];
    unsigned int incl = v;
    #pragma unroll
    for (int off = 1; off < 32; off <<= 1) {
        unsigned int n = __shfl_up_sync(0xFFFFFFFFu, incl, off);
        if (lane >= off) incl += n;
    }
    __shared__ unsigned int ws[32];
    if (lane == 31) ws[warp] = incl;
    __syncthreads();
    if (t < 32) {
        unsigned int w = ws[t];
        unsigned int iw = w;
        #pragma unroll
        for (int off = 1; off < 32; off <<= 1) {
            unsigned int n = __shfl_up_sync(0xFFFFFFFFu, iw, off);
            if (t >= off) iw += n;
        }
        ws[t] = iw - w;                     // exclusive warp base
        if (t == 31) g_bsum[sb] = iw;       // superblock total
    }
    __syncthreads();
    g_off[sb * K3A_TPB + t] = ws[warp] + (incl - v);
}

// K3b: one block scans the 200 superblock sums into exclusive bases.
__global__ void __launch_bounds__(256) k3b_base() {
    int t = threadIdx.x;
    int lane = t & 31;
    int warp = t >> 5;
    unsigned int v = (t < K3A_BLKS) ? g_bsum[t] : 0u;
    unsigned int incl = v;
    #pragma unroll
    for (int off = 1; off < 32; off <<= 1) {
        unsigned int n = __shfl_up_sync(0xFFFFFFFFu, incl, off);
        if (lane >= off) incl += n;
    }
    __shared__ unsigned int ws[8];
    if (lane == 31) ws[warp] = incl;
    __syncthreads();
    if (t < 8) {
        unsigned int w = ws[t];
        unsigned int iw = w;
        #pragma unroll
        for (int off = 1; off < 8; off <<= 1) {
            unsigned int n = __shfl_up_sync(0x000000FFu, iw, off);
            if (t >= off) iw += n;
        }
        ws[t] = iw - w;
    }
    __syncthreads();
    if (t < K3A_BLKS) g_bbase[t] = ws[warp] + (incl - v);
}

// ---------------------------------------------------------------------------
// K4: place each detection at its globally sorted position (R8-proven).
__global__ void __launch_bounds__(CHUNK_PIX) k4_write(float* __restrict__ out, int nmax) {
    int blk = blockIdx.x;
    int t = threadIdx.x;
    int b     = blk / NCHUNK;
    int chunk = blk - b * NCHUNK;
    int hw = chunk * CHUNK_PIX + t;
    int p  = b * HWn + hw;
    float h = (float)(hw / Wn);
    float w = (float)(hw % Wn);
    float* kp = out + 2u * (unsigned)nmax;
    #pragma unroll
    for (int slot = 0; slot < 2; slot++) {
        unsigned int rec = g_rec[2*p + slot];
        if (rec != 0xFFFFFFFFu) {
            unsigned int c    = rec >> 16;
            unsigned int rank = rec & 0xFFFFu;
            unsigned int idx  = (unsigned)((b * Cn + (int)c) * NCHUNK + chunk);
            unsigned int n = g_bbase[idx >> 10] + g_off[idx] + rank;
            if (n < (unsigned)nmax) {
                out[2u*n + 0u] = h;
                out[2u*n + 1u] = w;
                kp [2u*n + 0u] = 8.0f * h + 3.5f;   // ((p*2+.5)*2+.5)*2+.5
                kp [2u*n + 1u] = 8.0f * w + 3.5f;
            }
        }
    }
}

// ---------------------------------------------------------------------------
extern "C" void kernel_launch(void* const* d_in, const int* in_sizes, int n_in,
                              void* d_out, int out_size) {
    const float* x = (const float*)d_in[0];
    float* out = (float*)d_out;
    int nmax = out_size / 4;

    {   // K0: output padding (float4)
        int n4 = out_size / 4;
        int half4 = (out_size / 2) / 4;
        k0_init<<<(n4 + 255) / 256, 256>>>((float4*)out, n4, half4);
    }
    kfused<<<NBLK, TPB_F>>>(x);          // ONE 210MB pass, 4 threads/pixel
    k3a_scan<<<K3A_BLKS, K3A_TPB>>>();   // scan 204800 (b,c,chunk) counts
    k3b_base<<<1, 256>>>();              // 200 superblock bases
    k4_write<<<NBLK, CHUNK_PIX>>>(out, nmax);
}

// round 11
// speedup vs baseline: 5.3279x; 1.1033x over previous
#include <cuda_runtime.h>

// Problem constants
#define Bn 16
#define Cn 512
#define Hn 80
#define Wn 80
#define HWn (Hn*Wn)          // 6400
#define CHWn (Cn*HWn)        // 3276800
#define NPIX (Bn*HWn)        // 102400

// counting-sort chunks: 128 pixels per block, 8 channel-groups -> 1024 thr/blk
#define CHUNK_PIX 128
#define NGRP 8
#define GRP_C (Cn/NGRP)                 // 64 channels per group
#define TPB_F (CHUNK_PIX*NGRP)          // 1024
#define NCHUNK 50                       // chunks per batch (6400/128)
#define NBLK (Bn*NCHUNK)                // 800 blocks
#define NCNT (Bn*Cn*NCHUNK)             // 409600 counters, order (b,c,chunk)

// two-level scan of NCNT counters: 400 blocks x 1024 (exact)
#define K3A_BLKS 400
#define K3A_TPB 1024

// ---- scratch (allocation-free: __device__ globals) ----
__device__ unsigned int g_rec[NPIX * 2];   // 2 det slots/pixel: (c<<16)|rank, ~0u=empty
__device__ unsigned int g_cnt[NCNT];       // counts per (b,c,chunk)
__device__ unsigned int g_off[NCNT];       // exclusive within 1024-superblock
__device__ unsigned int g_bsum[K3A_BLKS];
__device__ unsigned int g_bbase[K3A_BLKS];

// ---------------------------------------------------------------------------
// K0: init output padding only
__global__ void k0_init(float4* __restrict__ out4, int n4, int half4) {
    int i = blockIdx.x * blockDim.x + threadIdx.x;
    if (i < half4) {
        out4[i] = make_float4(-1.f, -1.f, -1.f, -1.f);       // grid padding
    } else if (i < n4) {
        out4[i] = make_float4(-4.5f, -4.5f, -4.5f, -4.5f);   // 8*(-1)+3.5
    }
}

// ---------------------------------------------------------------------------
// neighbor test: v (>=0) must be >= all in-bounds raw 3x3 neighbors
// (v >= relu(n) <=> v >= n when v >= 0). Rare path.
__device__ __noinline__ bool neigh_ok(const float* __restrict__ plane,
                                      float v, int h, int w) {
    #pragma unroll
    for (int dh = -1; dh <= 1; dh++) {
        int nh = h + dh;
        if (nh < 0 || nh >= Hn) continue;
        #pragma unroll
        for (int dw = -1; dw <= 1; dw++) {
            if (dh == 0 && dw == 0) continue;
            int nw = w + dw;
            if (nw < 0 || nw >= Wn) continue;
            if (v < plane[nh * Wn + nw]) return false;
        }
    }
    return true;
}

// ---------------------------------------------------------------------------
// Fused: 8 threads per pixel (64 channels each), 128 pixels per block.
// Phase A: per-thread tie-tracking scan (R9/R10-proven accumulator logic).
// Merge:   leader thread per pixel combines 8 group results in ascending
//          group (= channel) order -> two smallest tied channels.
// Phase B: 3x3 local-max confirm per candidate channel (leaders).
// Phase C: counting-sort bookkeeping — R8/R10-proven verbatim.
__global__ void __launch_bounds__(TPB_F) kfused(const float* __restrict__ x) {
    __shared__ unsigned int s_mb[TPB_F];     // group max bits (relu >= 0)
    __shared__ unsigned int s_cand[TPB_F];   // cA | cB<<16 (0xFFFF = empty)
    __shared__ unsigned char s_nd[TPB_F];    // tie count (saturated at 3)
    __shared__ unsigned int bucket[Cn];      // per-channel counts, this chunk
    __shared__ unsigned int ch[CHUNK_PIX];   // packed det channels per pixel

    int blk = blockIdx.x;                    // 800
    int t = threadIdx.x;
    int pix = t & (CHUNK_PIX - 1);
    int grp = t >> 7;                        // 0..7
    int b     = blk / NCHUNK;
    int chunk = blk - b * NCHUNK;
    int hw = chunk * CHUNK_PIX + pix;
    int cbase = grp * GRP_C;
    const float* base = x + (size_t)b * CHWn + (size_t)cbase * HWn + hw;

    if (t < Cn) bucket[t] = 0u;

    // ---- Phase A: tie-tracking scan of 64 channels (4 accumulators) ----
    float m0 = 0.f, m1 = 0.f, m2 = 0.f, m3 = 0.f;
    int   a0 = -1,  a1 = -1,  a2 = -1,  a3 = -1;     // first tied channel
    int   b0 = -1,  b1 = -1,  b2 = -1,  b3 = -1;     // second tied channel
    int   n0 = 0,   n1 = 0,   n2 = 0,   n3 = 0;      // tie counts
    #pragma unroll 8
    for (int c = 0; c < GRP_C; c += 4) {
        float v0 = fmaxf(base[(size_t)(c+0) * HWn], 0.f);
        float v1 = fmaxf(base[(size_t)(c+1) * HWn], 0.f);
        float v2 = fmaxf(base[(size_t)(c+2) * HWn], 0.f);
        float v3 = fmaxf(base[(size_t)(c+3) * HWn], 0.f);
        if (v0 > m0)      { m0 = v0; a0 = cbase + c+0; n0 = 1; }
        else if (v0 == m0 && m0 > 0.f) { if (n0 == 1) b0 = cbase + c+0; n0++; }
        if (v1 > m1)      { m1 = v1; a1 = cbase + c+1; n1 = 1; }
        else if (v1 == m1 && m1 > 0.f) { if (n1 == 1) b1 = cbase + c+1; n1++; }
        if (v2 > m2)      { m2 = v2; a2 = cbase + c+2; n2 = 1; }
        else if (v2 == m2 && m2 > 0.f) { if (n2 == 1) b2 = cbase + c+2; n2++; }
        if (v3 > m3)      { m3 = v3; a3 = cbase + c+3; n3 = 1; }
        else if (v3 == m3 && m3 > 0.f) { if (n3 == 1) b3 = cbase + c+3; n3++; }
    }
    float m = fmaxf(fmaxf(m0, m1), fmaxf(m2, m3));

    // per-thread merge: two smallest tied channels within this group (proven)
    int cand[8];
    #pragma unroll
    for (int i = 0; i < 8; i++) cand[i] = 0x7FFFFFFF;
    int ndT = 0;
    if (m > 0.f) {
        if (m0 == m) { cand[0] = a0; if (n0 > 1) cand[1] = b0; ndT += n0; }
        if (m1 == m) { cand[2] = a1; if (n1 > 1) cand[3] = b1; ndT += n1; }
        if (m2 == m) { cand[4] = a2; if (n2 > 1) cand[5] = b2; ndT += n2; }
        if (m3 == m) { cand[6] = a3; if (n3 > 1) cand[7] = b3; ndT += n3; }
    }
    int cA = 0x7FFFFFFF, cB = 0x7FFFFFFF;
    #pragma unroll
    for (int i = 0; i < 8; i++) cA = min(cA, cand[i]);
    #pragma unroll
    for (int i = 0; i < 8; i++) if (cand[i] > cA) cB = min(cB, cand[i]);

    s_mb[t]   = __float_as_uint(m);
    s_cand[t] = (unsigned)(cA & 0xFFFF) | ((unsigned)(cB & 0xFFFF) << 16);
    s_nd[t]   = (unsigned char)min(ndT, 3);
    __syncthreads();

    // ---- leader merge + Phase B + Phase C front half ----
    unsigned int c0 = 0xFFFFu, c1 = 0xFFFFu;
    if (t < CHUNK_PIX) {
        unsigned int mb = 0u;
        #pragma unroll
        for (int g = 0; g < NGRP; g++) mb = max(mb, s_mb[g * CHUNK_PIX + t]);
        // collect candidates in ascending group (= channel) order
        unsigned int tA = 0xFFFFu, tB = 0xFFFFu;
        int ndtot = 0;
        if (mb != 0u) {                         // relu bits: 0 iff m == 0
            #pragma unroll
            for (int g = 0; g < NGRP; g++) {
                int gi = g * CHUNK_PIX + t;
                if (s_mb[gi] == mb) {
                    unsigned int pk = s_cand[gi];
                    unsigned int la = pk & 0xFFFFu, lb = pk >> 16;
                    if (la != 0xFFFFu) { if (tA == 0xFFFFu) tA = la; else if (tB == 0xFFFFu) tB = la; }
                    if (lb != 0xFFFFu) { if (tA == 0xFFFFu) tA = lb; else if (tB == 0xFFFFu) tB = lb; }
                    ndtot += (int)s_nd[gi];
                }
            }
        }
        float mv = __uint_as_float(mb);
        int h = hw / Wn, w = hw - (hw / Wn) * Wn;
        if (ndtot >= 1) {
            bool d0 = neigh_ok(x + (size_t)b * CHWn + (size_t)tA * HWn, mv, h, w);
            bool d1 = (ndtot >= 2) && (tB != 0xFFFFu) &&
                      neigh_ok(x + (size_t)b * CHWn + (size_t)tB * HWn, mv, h, w);
            if (d0) { c0 = tA; if (d1) c1 = tB; }
            else if (d1) { c0 = tB; }
        } else if (mb == 0u) {
            // degenerate pixel (all channels <= 0): prob 2^-512; exact rescan.
            int nd = 0;
            for (int c = 0; c < Cn && nd < 2; c++) {
                const float* plane = x + (size_t)b * CHWn + (size_t)c * HWn;
                if (fmaxf(plane[h * Wn + w], 0.f) == 0.f && neigh_ok(plane, 0.f, h, w)) {
                    if (nd == 0) c0 = (unsigned)c; else c1 = (unsigned)c;
                    nd++;
                }
            }
        }
        if (c0 != 0xFFFFu) atomicAdd(&bucket[c0], 1u);
        if (c1 != 0xFFFFu) atomicAdd(&bucket[c1], 1u);
        ch[t] = c0 | (c1 << 16);
    }
    __syncthreads();

    // ---- Phase C back half: exact pixel-order ranks (proven) ----
    if (t < CHUNK_PIX) {
        unsigned int r0 = 0, r1 = 0;
        if (c0 != 0xFFFFu) {
            for (int q = 0; q < t; q++) {
                unsigned int wv = ch[q];
                unsigned int lo = wv & 0xFFFFu, hi = wv >> 16;
                r0 += (lo == c0) + (hi == c0);
                r1 += (lo == c1) + (hi == c1);
            }
        }
        int p = b * HWn + hw;
        g_rec[2*p + 0] = (c0 != 0xFFFFu) ? ((c0 << 16) | r0) : 0xFFFFFFFFu;
        g_rec[2*p + 1] = (c1 != 0xFFFFu) ? ((c1 << 16) | r1) : 0xFFFFFFFFu;
    }
    if (t < Cn)
        g_cnt[(b * Cn + t) * NCHUNK + chunk] = bucket[t];
}

// ---------------------------------------------------------------------------
// K3a: 400 blocks x 1024 counts (1/thread): local exclusive scan + block sum.
__global__ void __launch_bounds__(K3A_TPB) k3a_scan() {
    int sb = blockIdx.x;
    int t = threadIdx.x;
    int lane = t & 31;
    int warp = t >> 5;
    unsigned int v = g_cnt[sb * K3A_TPB + t];
    unsigned int incl = v;
    #pragma unroll
    for (int off = 1; off < 32; off <<= 1) {
        unsigned int n = __shfl_up_sync(0xFFFFFFFFu, incl, off);
        if (lane >= off) incl += n;
    }
    __shared__ unsigned int ws[32];
    if (lane == 31) ws[warp] = incl;
    __syncthreads();
    if (t < 32) {
        unsigned int w = ws[t];
        unsigned int iw = w;
        #pragma unroll
        for (int off = 1; off < 32; off <<= 1) {
            unsigned int n = __shfl_up_sync(0xFFFFFFFFu, iw, off);
            if (t >= off) iw += n;
        }
        ws[t] = iw - w;                     // exclusive warp base
        if (t == 31) g_bsum[sb] = iw;       // superblock total
    }
    __syncthreads();
    g_off[sb * K3A_TPB + t] = ws[warp] + (incl - v);
}

// K3b: one block (512 threads) scans the 400 superblock sums (R9-proven).
__global__ void __launch_bounds__(512) k3b_base() {
    int t = threadIdx.x;
    int lane = t & 31;
    int warp = t >> 5;                      // 16 warps
    unsigned int v = (t < K3A_BLKS) ? g_bsum[t] : 0u;
    unsigned int incl = v;
    #pragma unroll
    for (int off = 1; off < 32; off <<= 1) {
        unsigned int n = __shfl_up_sync(0xFFFFFFFFu, incl, off);
        if (lane >= off) incl += n;
    }
    __shared__ unsigned int ws[16];
    if (lane == 31) ws[warp] = incl;
    __syncthreads();
    if (t < 32) {                           // warp 0 scans 16 warp sums
        unsigned int wv = (t < 16) ? ws[t] : 0u;
        unsigned int iw = wv;
        #pragma unroll
        for (int off = 1; off < 32; off <<= 1) {
            unsigned int n = __shfl_up_sync(0xFFFFFFFFu, iw, off);
            if (t >= off) iw += n;
        }
        if (t < 16) ws[t] = iw - wv;
    }
    __syncthreads();
    if (t < K3A_BLKS) g_bbase[t] = ws[warp] + (incl - v);
}

// ---------------------------------------------------------------------------
// K4: place each detection at its globally sorted position (proven).
__global__ void __launch_bounds__(CHUNK_PIX) k4_write(float* __restrict__ out, int nmax) {
    int blk = blockIdx.x;
    int t = threadIdx.x;
    int b     = blk / NCHUNK;
    int chunk = blk - b * NCHUNK;
    int hw = chunk * CHUNK_PIX + t;
    int p  = b * HWn + hw;
    float h = (float)(hw / Wn);
    float w = (float)(hw % Wn);
    float* kp = out + 2u * (unsigned)nmax;
    #pragma unroll
    for (int slot = 0; slot < 2; slot++) {
        unsigned int rec = g_rec[2*p + slot];
        if (rec != 0xFFFFFFFFu) {
            unsigned int c    = rec >> 16;
            unsigned int rank = rec & 0xFFFFu;
            unsigned int idx  = (unsigned)((b * Cn + (int)c) * NCHUNK + chunk);
            unsigned int n = g_bbase[idx >> 10] + g_off[idx] + rank;
            if (n < (unsigned)nmax) {
                out[2u*n + 0u] = h;
                out[2u*n + 1u] = w;
                kp [2u*n + 0u] = 8.0f * h + 3.5f;   // ((p*2+.5)*2+.5)*2+.5
                kp [2u*n + 1u] = 8.0f * w + 3.5f;
            }
        }
    }
}

// ---------------------------------------------------------------------------
extern "C" void kernel_launch(void* const* d_in, const int* in_sizes, int n_in,
                              void* d_out, int out_size) {
    const float* x = (const float*)d_in[0];
    float* out = (float*)d_out;
    int nmax = out_size / 4;

    {   // K0: output padding (float4)
        int n4 = out_size / 4;
        int half4 = (out_size / 2) / 4;
        k0_init<<<(n4 + 255) / 256, 256>>>((float4*)out, n4, half4);
    }
    kfused<<<NBLK, TPB_F>>>(x);          // ONE 210MB pass, 8 threads/pixel
    k3a_scan<<<K3A_BLKS, K3A_TPB>>>();   // scan 409600 (b,c,chunk) counts
    k3b_base<<<1, 512>>>();              // 400 superblock bases
    k4_write<<<NBLK, CHUNK_PIX>>>(out, nmax);
}